// round 9
// baseline (speedup 1.0000x reference)
#include <cuda_runtime.h>

#define SEQ   600
#define BATCH 4096
#define INP   6
#define HID   30
#define OUTD  61
#define VLEN  36              // x(6) + h(30)
#define NTHR  256             // 8 warps
#define WPB   8               // warps per block
#define BPW   4               // batches per warp
#define BBLK  (WPB * BPW)     // 32 batches per block
#define NBLK  (BATCH / BBLK)  // 128 blocks

typedef unsigned long long ull;

// ---------------- preprocessed weights (device globals) ----------------
__device__ __align__(16) float g_W[4][32][VLEN];  // [gate][unit][ x(6) | h(30) ]
__device__ float g_bias[4][32];                   // b_ih + b_hh (0 for pad units)
__device__ float g_M[HID][OUTD];                  // fused fc1+fc2
__device__ float g_bv[OUTD];                      // b2 + b1 @ W2^T

// ---------------- helpers ----------------
__device__ __forceinline__ void ffma2(ull& acc, ull a, ull b) {
    asm("fma.rn.f32x2 %0, %1, %2, %0;" : "+l"(acc) : "l"(a), "l"(b));
}
__device__ __forceinline__ ull pack2(float x, float y) {
    ull r; asm("mov.b64 %0, {%1, %2};" : "=l"(r) : "f"(x), "f"(y)); return r;
}
__device__ __forceinline__ float hsum2(ull v) {
    float2 r; asm("mov.b64 {%0, %1}, %2;" : "=f"(r.x), "=f"(r.y) : "l"(v));
    return r.x + r.y;
}
__device__ __forceinline__ float tanh_fast(float x) {
    float r; asm("tanh.approx.f32 %0, %1;" : "=f"(r) : "f"(x)); return r;
}
__device__ __forceinline__ float sigmoid_fast(float x) {
    return fmaf(0.5f, tanh_fast(0.5f * x), 0.5f);
}

// ---------------- prep kernel ----------------
__global__ void prep_kernel(const float* __restrict__ Wih, const float* __restrict__ Whh,
                            const float* __restrict__ bih, const float* __restrict__ bhh,
                            const float* __restrict__ W1,  const float* __restrict__ b1,
                            const float* __restrict__ W2,  const float* __restrict__ b2) {
    int tid = threadIdx.x;
    for (int idx = tid; idx < 4 * 32 * VLEN; idx += blockDim.x) {
        int g = idx / (32 * VLEN);
        int r = idx % (32 * VLEN);
        int u = r / VLEN, j = r % VLEN;
        float w = 0.0f;
        if (u < HID) {
            if (j < INP) w = Wih[(g * HID + u) * INP + j];
            else         w = Whh[(g * HID + u) * HID + (j - INP)];
        }
        g_W[g][u][j] = w;
    }
    for (int idx = tid; idx < 4 * 32; idx += blockDim.x) {
        int g = idx / 32, u = idx % 32;
        g_bias[g][u] = (u < HID) ? (bih[g * HID + u] + bhh[g * HID + u]) : 0.0f;
    }
    for (int idx = tid; idx < HID * OUTD; idx += blockDim.x) {
        int j = idx / OUTD, o = idx % OUTD;
        float s = 0.0f;
        for (int k = 0; k < HID; k++) s += W1[k * HID + j] * W2[o * HID + k];
        g_M[j][o] = s;
    }
    for (int o = tid; o < OUTD; o += blockDim.x) {
        float s = b2[o];
        for (int k = 0; k < HID; k++) s += b1[k] * W2[o * HID + k];
        g_bv[o] = s;
    }
}

// load one batch's h row (30 floats) into 15 ull regs (7x LDS.128 + 1x LDS.64)
__device__ __forceinline__ void load_h(const float* __restrict__ hrow, ull* vh) {
    const ulonglong2* h2 = (const ulonglong2*)hrow;
#pragma unroll
    for (int k = 0; k < 7; k++) { ulonglong2 t = h2[k]; vh[2 * k] = t.x; vh[2 * k + 1] = t.y; }
    vh[14] = *(const ull*)(hrow + 28);
}

// full 4-gate MAC for one batch: x part (3 ull) + h part (15 ull)
__device__ __forceinline__ void mac_batch(const ull w[4][18], const ull bias2[4],
                                          const float* __restrict__ xr, const ull* vh,
                                          ull* acc /*[4]*/) {
    ull a0 = bias2[0], a1 = bias2[1], a2 = bias2[2], a3 = bias2[3];
    ull vx0 = *(const ull*)(xr);
    ull vx1 = *(const ull*)(xr + 2);
    ull vx2 = *(const ull*)(xr + 4);
    ffma2(a0, w[0][0], vx0); ffma2(a1, w[1][0], vx0);
    ffma2(a2, w[2][0], vx0); ffma2(a3, w[3][0], vx0);
    ffma2(a0, w[0][1], vx1); ffma2(a1, w[1][1], vx1);
    ffma2(a2, w[2][1], vx1); ffma2(a3, w[3][1], vx1);
    ffma2(a0, w[0][2], vx2); ffma2(a1, w[1][2], vx2);
    ffma2(a2, w[2][2], vx2); ffma2(a3, w[3][2], vx2);
#pragma unroll
    for (int k = 0; k < 15; k++) {
        ull v = vh[k];
        ffma2(a0, w[0][3 + k], v); ffma2(a1, w[1][3 + k], v);
        ffma2(a2, w[2][3 + k], v); ffma2(a3, w[3][3 + k], v);
    }
    acc[0] = a0; acc[1] = a1; acc[2] = a2; acc[3] = a3;
}

// activation + state update for one batch
__device__ __forceinline__ float act_batch(const ull* acc, float& c) {
    float si = sigmoid_fast(hsum2(acc[0]));
    float sf = sigmoid_fast(hsum2(acc[1]));
    float tg = tanh_fast   (hsum2(acc[2]));
    float so = sigmoid_fast(hsum2(acc[3]));
    c = fmaf(sf, c, si * tg);
    return so * tanh_fast(c);
}

// ---------------- main persistent LSTM kernel (warp-autonomous, 2-stage pipeline) ----------------
__global__ void __launch_bounds__(NTHR, 1)
lstm_kernel(const float* __restrict__ X, float* __restrict__ out) {
    __shared__ __align__(16) float hb[2][WPB][BPW][32];   // 8192 B, h double-buffered
    __shared__ __align__(16) float xb[WPB][2][BPW * INP]; // 1536 B, x double-buffered

    const int tid    = threadIdx.x;
    const int lane   = tid & 31;                 // unit 0..31 (30 real, 2 pad)
    const int wid    = tid >> 5;                 // warp 0..7
    const int bfirst = (blockIdx.x * WPB + wid) * BPW;
    const bool xlane = (lane < BPW * INP / 4);   // lanes 0..5 stage x

    // ---- weights for (all 4 gates, unit=lane): 4 x 18 ull = 144 regs ----
    ull w[4][18];
    ull bias2[4];
#pragma unroll
    for (int g = 0; g < 4; g++) {
        const ull* wp = (const ull*)&g_W[g][lane][0];
#pragma unroll
        for (int k = 0; k < 18; k++) w[g][k] = wp[k];
        bias2[g] = pack2(g_bias[g][lane], 0.0f);
    }

    // ---- init ----
#pragma unroll
    for (int b = 0; b < BPW; b++) hb[0][wid][b][lane] = 0.0f;
    if (xlane) {
        const float4 v = *(const float4*)(X + (size_t)bfirst * INP + lane * 4);
        *(float4*)&xb[wid][0][lane * 4] = v;
    }
    __syncwarp();

    float c[BPW] = {0.0f, 0.0f, 0.0f, 0.0f};

    int cur = 0;
#pragma unroll 1
    for (int t = 0; t < SEQ; ++t) {
        // prefetch x(t+1)
        float4 xp;
        const int tn = (t + 1 < SEQ) ? t + 1 : t;
        if (xlane)
            xp = *(const float4*)(X + ((size_t)tn * BATCH + bfirst) * INP + lane * 4);

        const float* xr = &xb[wid][t & 1][0];
        const float* hc = &hb[cur][wid][0][0];
        float*       hn = &hb[cur ^ 1][wid][0][0];

        // ===== stage A: load+MAC batches 0,1 =====
        ull vhA[2][15];
        load_h(hc + 0 * 32, vhA[0]);
        load_h(hc + 1 * 32, vhA[1]);
        ull accA[2][4];
        mac_batch(w, bias2, xr + 0 * INP, vhA[0], accA[0]);
        mac_batch(w, bias2, xr + 1 * INP, vhA[1], accA[1]);

        // hoist stage-B h loads BEFORE any STS (aliasing: STS would block later LDS)
        ull vhB[2][15];
        load_h(hc + 2 * 32, vhB[0]);
        load_h(hc + 3 * 32, vhB[1]);

        // stage-A activations + stores (overlap with stage-B MACs below)
        float h0 = act_batch(accA[0], c[0]);
        float h1 = act_batch(accA[1], c[1]);
        hn[0 * 32 + lane] = h0;
        hn[1 * 32 + lane] = h1;

        // ===== stage B: MAC batches 2,3 (from pre-loaded regs), then activate =====
        ull accB[2][4];
        mac_batch(w, bias2, xr + 2 * INP, vhB[0], accB[0]);
        mac_batch(w, bias2, xr + 3 * INP, vhB[1], accB[1]);
        float h2 = act_batch(accB[0], c[2]);
        float h3 = act_batch(accB[1], c[3]);
        hn[2 * 32 + lane] = h2;
        hn[3 * 32 + lane] = h3;

        // publish x(t+1)
        if (xlane) *(float4*)&xb[wid][(t + 1) & 1][lane * 4] = xp;
        __syncwarp();
        cur ^= 1;
    }

    // ---- fused fc1+fc2 epilogue over the block's 32 batches ----
    __syncthreads();
    for (int idx = tid; idx < BBLK * OUTD; idx += NTHR) {
        int lb = idx / OUTD, o = idx % OUTD;
        int ww = lb / BPW, b = lb % BPW;
        float s = g_bv[o];
#pragma unroll
        for (int j = 0; j < HID; j++) s += hb[cur][ww][b][j] * g_M[j][o];
        out[(size_t)(blockIdx.x * BBLK + lb) * OUTD + o] = s;
    }
}

// ---------------- launch ----------------
extern "C" void kernel_launch(void* const* d_in, const int* in_sizes, int n_in,
                              void* d_out, int out_size) {
    const float* X   = (const float*)d_in[0];
    const float* Wih = (const float*)d_in[1];
    const float* Whh = (const float*)d_in[2];
    const float* bih = (const float*)d_in[3];
    const float* bhh = (const float*)d_in[4];
    const float* W1  = (const float*)d_in[5];
    const float* b1  = (const float*)d_in[6];
    const float* W2  = (const float*)d_in[7];
    const float* b2  = (const float*)d_in[8];

    prep_kernel<<<1, 256>>>(Wih, Whh, bih, bhh, W1, b1, W2, b2);
    lstm_kernel<<<NBLK, NTHR>>>(X, (float*)d_out);
}